// round 3
// baseline (speedup 1.0000x reference)
#include <cuda_runtime.h>

// ComplexSuperposition: B=128, T=128, D=512
// out_r[b,d] = sum_t real[b,t,d] * w[b,t]
// out_i[b,d] = sum_t imag[b,t,d] * w[b,t]
// output_r[b,i,j] = out_r[b,i]*out_r[b,j] + out_i[b,i]*out_i[b,j]
// output_i[b,i,j] = out_i[b,i]*out_r[b,j] - out_r[b,i]*out_i[b,j]
// d_out layout: [output_r (128*512*512 f32)] then [output_i (128*512*512 f32)]

#define BB 128
#define TT 128
#define DD 512

// scratch (allocation-free rule: device globals)
__device__ float g_outr[BB * DD];
__device__ float g_outi[BB * DD];

__global__ void __launch_bounds__(256) reduce_k(const float* __restrict__ re,
                                                const float* __restrict__ im,
                                                const float* __restrict__ w) {
    int idx = blockIdx.x * blockDim.x + threadIdx.x;   // 0 .. B*D-1 = 65535
    int b = idx >> 9;            // / 512
    int d = idx & (DD - 1);
    const float* rp = re + (size_t)b * TT * DD + d;
    const float* ip = im + (size_t)b * TT * DD + d;
    const float* wp = w + b * TT;
    float ar = 0.f, ai = 0.f;
#pragma unroll 8
    for (int t = 0; t < TT; ++t) {
        float wt = __ldg(wp + t);          // uniform across warp -> broadcast
        ar = fmaf(__ldg(rp + (size_t)t * DD), wt, ar);
        ai = fmaf(__ldg(ip + (size_t)t * DD), wt, ai);
    }
    g_outr[idx] = ar;
    g_outi[idx] = ai;
}

// One block = one batch b, one 16-row tile of i. 32 tiles per batch.
// 256 threads: j4 = tid & 127 (float4 column), ih = tid >> 7 (row pair half).
__global__ void __launch_bounds__(256) outer_k(float* __restrict__ out) {
    __shared__ float4 sr4[DD / 4];
    __shared__ float4 si4[DD / 4];

    int b    = blockIdx.x >> 5;
    int tile = blockIdx.x & 31;
    int tid  = threadIdx.x;

    const float4* gr = (const float4*)(g_outr + b * DD);
    const float4* gi = (const float4*)(g_outi + b * DD);
    if (tid < 128) sr4[tid] = gr[tid];
    else           si4[tid - 128] = gi[tid - 128];
    __syncthreads();

    const float* srf = (const float*)sr4;
    const float* sif = (const float*)si4;

    int j4 = tid & 127;
    int ih = tid >> 7;

    // column vectors, hoisted out of the row loop
    float4 br = sr4[j4];
    float4 bi = si4[j4];

    float4* outr = (float4*)(out + (size_t)b * DD * DD) + (size_t)(tile * 16) * 128 + j4;
    float4* outi = outr + (size_t)BB * DD * DD / 4;   // output_i half

#pragma unroll
    for (int k = 0; k < 8; ++k) {
        int row = k * 2 + ih;                 // 0..15 within tile
        int i   = tile * 16 + row;            // global row index 0..511
        float ar = srf[i];                    // warp-uniform broadcast
        float ai = sif[i];
        float4 vr, vi;
        vr.x = fmaf(ar, br.x, ai * bi.x);
        vr.y = fmaf(ar, br.y, ai * bi.y);
        vr.z = fmaf(ar, br.z, ai * bi.z);
        vr.w = fmaf(ar, br.w, ai * bi.w);
        vi.x = fmaf(ai, br.x, -ar * bi.x);
        vi.y = fmaf(ai, br.y, -ar * bi.y);
        vi.z = fmaf(ai, br.z, -ar * bi.z);
        vi.w = fmaf(ai, br.w, -ar * bi.w);
        outr[(size_t)row * 128] = vr;
        outi[(size_t)row * 128] = vi;
    }
}

extern "C" void kernel_launch(void* const* d_in, const int* in_sizes, int n_in,
                              void* d_out, int out_size) {
    const float* re = (const float*)d_in[0];   // input_real [128,128,512]
    const float* im = (const float*)d_in[1];   // input_imag [128,128,512]
    const float* w  = (const float*)d_in[2];   // weight     [128,128]
    float* out = (float*)d_out;                // [2,128,512,512]

    reduce_k<<<(BB * DD) / 256, 256>>>(re, im, w);
    outer_k<<<BB * 32, 256>>>(out);
}

// round 6
// speedup vs baseline: 1.2140x; 1.2140x over previous
#include <cuda_runtime.h>

// ComplexSuperposition: B=128, T=128, D=512
// out_r[b,d] = sum_t real[b,t,d] * w[b,t]
// out_i[b,d] = sum_t imag[b,t,d] * w[b,t]
// output_r[b,i,j] = out_r[b,i]*out_r[b,j] + out_i[b,i]*out_i[b,j]
// output_i[b,i,j] = out_i[b,i]*out_r[b,j] - out_r[b,i]*out_i[b,j]
// d_out layout: [output_r (128*512*512 f32)] then [output_i (...)]

#define BB 128
#define TT 128
#define DD 512

__device__ float g_outr[BB * DD];
__device__ float g_outi[BB * DD];

// grid = B * (D/128) = 512 blocks, 256 threads.
// tid: j = tid & 31 (float4 lane over 128-float chunk), tg = tid >> 5 (T split 0..7).
// Each thread reduces 16 t's with float4 loads; shared combine across the 8 groups.
__global__ void __launch_bounds__(256) reduce_k(const float* __restrict__ re,
                                                const float* __restrict__ im,
                                                const float* __restrict__ w) {
    __shared__ float4 sr[8][32];
    __shared__ float4 si[8][32];

    int b     = blockIdx.x >> 2;          // / 4
    int chunk = blockIdx.x & 3;           // which 128-float chunk of D
    int tid   = threadIdx.x;
    int j     = tid & 31;
    int tg    = tid >> 5;

    // float4 index of this thread's column within the batch
    size_t base4 = ((size_t)b * TT * DD + chunk * 128 + j * 4) >> 2;
    const float4* rp = (const float4*)re + base4;
    const float4* ip = (const float4*)im + base4;
    const float*  wp = w + b * TT;

    float4 ar = make_float4(0.f, 0.f, 0.f, 0.f);
    float4 ai = make_float4(0.f, 0.f, 0.f, 0.f);

    int t0 = tg * 16;
#pragma unroll 16
    for (int k = 0; k < 16; ++k) {
        int t = t0 + k;
        float  wt = __ldg(wp + t);                    // uniform broadcast
        float4 r  = __ldg(rp + (size_t)t * (DD / 4));
        float4 i4 = __ldg(ip + (size_t)t * (DD / 4));
        ar.x = fmaf(r.x, wt, ar.x);  ar.y = fmaf(r.y, wt, ar.y);
        ar.z = fmaf(r.z, wt, ar.z);  ar.w = fmaf(r.w, wt, ar.w);
        ai.x = fmaf(i4.x, wt, ai.x); ai.y = fmaf(i4.y, wt, ai.y);
        ai.z = fmaf(i4.z, wt, ai.z); ai.w = fmaf(i4.w, wt, ai.w);
    }

    sr[tg][j] = ar;
    si[tg][j] = ai;
    __syncthreads();

    if (tid < 64) {
        int q = tid >> 5;        // 0 = real, 1 = imag
        int l = tid & 31;
        float4 acc = make_float4(0.f, 0.f, 0.f, 0.f);
#pragma unroll
        for (int k = 0; k < 8; ++k) {
            float4 v = q ? si[k][l] : sr[k][l];
            acc.x += v.x; acc.y += v.y; acc.z += v.z; acc.w += v.w;
        }
        float4* dst = (float4*)(q ? g_outi : g_outr);
        dst[((size_t)b * DD + chunk * 128 + l * 4) >> 2] = acc;
    }
}

// One block = one batch b, one 16-row tile of i. 32 tiles per batch.
__global__ void __launch_bounds__(256) outer_k(float* __restrict__ out) {
    __shared__ float4 sr4[DD / 4];
    __shared__ float4 si4[DD / 4];

    int b    = blockIdx.x >> 5;
    int tile = blockIdx.x & 31;
    int tid  = threadIdx.x;

    const float4* gr = (const float4*)(g_outr + b * DD);
    const float4* gi = (const float4*)(g_outi + b * DD);
    if (tid < 128) sr4[tid] = gr[tid];
    else           si4[tid - 128] = gi[tid - 128];
    __syncthreads();

    const float* srf = (const float*)sr4;
    const float* sif = (const float*)si4;

    int j4 = tid & 127;
    int ih = tid >> 7;

    float4 br = sr4[j4];
    float4 bi = si4[j4];

    float4* outr = (float4*)(out + (size_t)b * DD * DD) + (size_t)(tile * 16) * 128 + j4;
    float4* outi = outr + (size_t)BB * DD * DD / 4;

#pragma unroll
    for (int k = 0; k < 8; ++k) {
        int row = k * 2 + ih;
        int i   = tile * 16 + row;
        float ar = srf[i];
        float ai = sif[i];
        float4 vr, vi;
        vr.x = fmaf(ar, br.x, ai * bi.x);
        vr.y = fmaf(ar, br.y, ai * bi.y);
        vr.z = fmaf(ar, br.z, ai * bi.z);
        vr.w = fmaf(ar, br.w, ai * bi.w);
        vi.x = fmaf(ai, br.x, -ar * bi.x);
        vi.y = fmaf(ai, br.y, -ar * bi.y);
        vi.z = fmaf(ai, br.z, -ar * bi.z);
        vi.w = fmaf(ai, br.w, -ar * bi.w);
        __stcs(&outr[(size_t)row * 128], vr);   // streaming: never re-read
        __stcs(&outi[(size_t)row * 128], vi);
    }
}

extern "C" void kernel_launch(void* const* d_in, const int* in_sizes, int n_in,
                              void* d_out, int out_size) {
    const float* re = (const float*)d_in[0];   // input_real [128,128,512]
    const float* im = (const float*)d_in[1];   // input_imag [128,128,512]
    const float* w  = (const float*)d_in[2];   // weight     [128,128]
    float* out = (float*)d_out;                // [2,128,512,512]

    reduce_k<<<BB * 4, 256>>>(re, im, w);
    outer_k<<<BB * 32, 256>>>(out);
}